// round 8
// baseline (speedup 1.0000x reference)
#include <cuda_runtime.h>

// Problem constants
#define BQ 4          // batch
#define NP 16384      // points
#define NQ 4096       // queries (npoint)
#define CF 64         // feature channels
#define KS 32         // nsample
#define OUTC (CF + 3) // 67 output channels

#define WPB 8         // warps per block
#define QPW 2         // queries per warp
#define NSPLIT 2      // point-dimension splits
#define HALF (NP / NSPLIT)
#define TILE 2048     // shared-memory tile of points
#define CAP 96        // per-(warp,query) candidate buffer (31 carry + 64 new)

#define FULLM 0xffffffffu
// +inf distance, max index: any real key sorts below this.
#define INFKEY 0x7f800000ffffffffULL

// Scratch: partial top-32 keys (8 MB) + transposed features (16 MB).
__device__ unsigned long long g_pk[(size_t)BQ * NQ * NSPLIT * KS];
__device__ float g_ft[(size_t)BQ * NP * CF];   // (B, N, C)

typedef unsigned long long u64;

__device__ __forceinline__ u64 pack_key(float d, int idx) {
    return ((u64)__float_as_uint(d) << 32) | (unsigned int)idx;
}

// ---- packed f32x2 helpers (sm_103a) ----
__device__ __forceinline__ u64 f2_add(u64 a, u64 b) {
    u64 r; asm("add.rn.f32x2 %0, %1, %2;" : "=l"(r) : "l"(a), "l"(b)); return r;
}
__device__ __forceinline__ u64 f2_mul(u64 a, u64 b) {
    u64 r; asm("mul.rn.f32x2 %0, %1, %2;" : "=l"(r) : "l"(a), "l"(b)); return r;
}
__device__ __forceinline__ u64 f2_fma(u64 a, u64 b, u64 c) {
    u64 r; asm("fma.rn.f32x2 %0, %1, %2, %3;" : "=l"(r) : "l"(a), "l"(b), "l"(c)); return r;
}
__device__ __forceinline__ u64 f2_bcast(float x) {
    u64 r; asm("mov.b64 %0, {%1, %1};" : "=l"(r) : "f"(x)); return r;
}
__device__ __forceinline__ void f2_unpack(u64 v, float& lo, float& hi) {
    asm("mov.b64 {%0, %1}, %2;" : "=f"(lo), "=f"(hi) : "l"(v));
}

// Warp-wide bitonic sort, ascending, one key per lane.
__device__ __forceinline__ u64 warp_bitonic_sort(u64 key, int lane) {
#pragma unroll
    for (int k = 2; k <= 32; k <<= 1) {
#pragma unroll
        for (int j = k >> 1; j > 0; j >>= 1) {
            u64 other = __shfl_xor_sync(FULLM, key, j);
            bool take_min = (((lane & k) == 0) == ((lane & j) == 0));
            bool lt = key < other;
            key = (take_min == lt) ? key : other;
        }
    }
    return key;
}

// Keep lowest 32 of (top asc-sorted) U (cand asc-sorted), result asc-sorted.
__device__ __forceinline__ u64 warp_merge_topk(u64 top, u64 cand, int lane) {
    u64 crev = __shfl_sync(FULLM, cand, 31 - lane);
    u64 v = (top < crev) ? top : crev;   // bitonic sequence = lowest 32
#pragma unroll
    for (int j = 16; j > 0; j >>= 1) {   // bitonic cleanup
        u64 other = __shfl_xor_sync(FULLM, v, j);
        bool lower = (lane & j) == 0;
        bool lt = v < other;
        v = (lower == lt) ? v : other;
    }
    return v;
}

// Fold full 32-candidate batches from buf into (top, thf).
__device__ __forceinline__ void fold32(u64* buf, int& cnt, u64& top,
                                       float& thf, int lane) {
    while (cnt >= 32) {   // take LAST 32 (order irrelevant: batch gets sorted)
        u64 c = buf[cnt - 32 + lane];
        c   = warp_bitonic_sort(c, lane);
        top = warp_merge_topk(top, c, lane);
        cnt -= 32;
        thf = __uint_as_float((unsigned)(__shfl_sync(FULLM, top, 31) >> 32));
    }
}

// Compact passing lanes of one point-group into buf via ballot m.
#define PUSHM(buf, cnt, m, pred, dval, idxval)                                 \
    do {                                                                       \
        if (pred) (buf)[(cnt) + __popc((m) & ltmask)] = pack_key(dval, idxval);\
        (cnt) += __popc(m);                                                    \
    } while (0)

// ---------------------------------------------------------------------------
// Kernel 1: exact PARTIAL KNN over an 8192-point split, one WARP per TWO
// queries. Tile read (3x LDS.128 / 128 pts) amortized over 256 query-points.
// Distances via packed f32x2 fma on negated SoA tiles. Emits sorted u64
// (dist,idx) keys; two splits merged exactly in group_kernel. The strict
// 'd < thf' filter is exact per split: within a split the scan is ascending
// in index, so an equal-distance later candidate loses the (dist,idx) tie.
// ---------------------------------------------------------------------------
__global__ __launch_bounds__(WPB * 32)
void knn_kernel(const float* __restrict__ xyz,
                const float* __restrict__ new_xyz) {
    const int split = blockIdx.y;
    const int b     = blockIdx.z;
    const int warp  = threadIdx.x >> 5;
    const int lane  = threadIdx.x & 31;
    const int q0    = (blockIdx.x * WPB + warp) * QPW;
    const unsigned ltmask = (1u << lane) - 1u;

    const float* qp = new_xyz + ((size_t)b * NQ + q0) * 3;
    const u64 qxx0 = f2_bcast(qp[0]), qyy0 = f2_bcast(qp[1]), qzz0 = f2_bcast(qp[2]);
    const u64 qxx1 = f2_bcast(qp[3]), qyy1 = f2_bcast(qp[4]), qzz1 = f2_bcast(qp[5]);

    __shared__ float s_x[TILE], s_y[TILE], s_z[TILE];  // 24 KB (negated)
    __shared__ u64   s_cand[WPB][QPW][CAP];            // 12 KB

    u64 top0 = INFKEY, top1 = INFKEY;
    float thf0 = __int_as_float(0x7f800000);
    float thf1 = __int_as_float(0x7f800000);
    int cnt0 = 0, cnt1 = 0;

    const int pbase = split * HALF;

    for (int t0 = 0; t0 < HALF; t0 += TILE) {
        __syncthreads();
        {
            const float* src = xyz + ((size_t)b * NP + pbase + t0) * 3;
#pragma unroll
            for (int k = 0; k < TILE / (WPB * 32); k++) {
                const int pt = threadIdx.x + k * (WPB * 32);
                s_x[pt] = -src[pt * 3];
                s_y[pt] = -src[pt * 3 + 1];
                s_z[pt] = -src[pt * 3 + 2];
            }
        }
        __syncthreads();

#pragma unroll 2
        for (int j = 0; j < TILE; j += 128) {
            const int o = j + 4 * lane;
            const ulonglong2 xs = *(const ulonglong2*)(s_x + o);
            const ulonglong2 ys = *(const ulonglong2*)(s_y + o);
            const ulonglong2 zs = *(const ulonglong2*)(s_z + o);

            // query 0 distances
            u64 a01, a23;
            {
                const u64 dx01 = f2_add(qxx0, xs.x), dx23 = f2_add(qxx0, xs.y);
                const u64 dy01 = f2_add(qyy0, ys.x), dy23 = f2_add(qyy0, ys.y);
                const u64 dz01 = f2_add(qzz0, zs.x), dz23 = f2_add(qzz0, zs.y);
                a01 = f2_mul(dz01, dz01);
                a23 = f2_mul(dz23, dz23);
                a01 = f2_fma(dy01, dy01, a01);
                a23 = f2_fma(dy23, dy23, a23);
                a01 = f2_fma(dx01, dx01, a01);
                a23 = f2_fma(dx23, dx23, a23);
            }
            // query 1 distances
            u64 b01, b23;
            {
                const u64 dx01 = f2_add(qxx1, xs.x), dx23 = f2_add(qxx1, xs.y);
                const u64 dy01 = f2_add(qyy1, ys.x), dy23 = f2_add(qyy1, ys.y);
                const u64 dz01 = f2_add(qzz1, zs.x), dz23 = f2_add(qzz1, zs.y);
                b01 = f2_mul(dz01, dz01);
                b23 = f2_mul(dz23, dz23);
                b01 = f2_fma(dy01, dy01, b01);
                b23 = f2_fma(dy23, dy23, b23);
                b01 = f2_fma(dx01, dx01, b01);
                b23 = f2_fma(dx23, dx23, b23);
            }

            float d0, d1, d2, d3, e0, e1, e2, e3;
            f2_unpack(a01, d0, d1);  f2_unpack(a23, d2, d3);
            f2_unpack(b01, e0, e1);  f2_unpack(b23, e2, e3);

            const bool hit0 = fminf(fminf(d0, d1), fminf(d2, d3)) < thf0;
            const bool hit1 = fminf(fminf(e0, e1), fminf(e2, e3)) < thf1;
            if (__any_sync(FULLM, hit0 | hit1)) {
                const int gi = pbase + t0 + o;
                // query 0 (gated: ballot of the group-hit is the gate)
                if (__ballot_sync(FULLM, hit0)) {
                    const bool p0 = d0 < thf0, p1 = d1 < thf0;
                    unsigned m0 = __ballot_sync(FULLM, p0);
                    unsigned m1 = __ballot_sync(FULLM, p1);
                    PUSHM(s_cand[warp][0], cnt0, m0, p0, d0, gi);
                    PUSHM(s_cand[warp][0], cnt0, m1, p1, d1, gi + 1);
                    __syncwarp(FULLM);
                    fold32(s_cand[warp][0], cnt0, top0, thf0, lane);
                    const bool p2 = d2 < thf0, p3 = d3 < thf0;
                    unsigned m2 = __ballot_sync(FULLM, p2);
                    unsigned m3 = __ballot_sync(FULLM, p3);
                    PUSHM(s_cand[warp][0], cnt0, m2, p2, d2, gi + 2);
                    PUSHM(s_cand[warp][0], cnt0, m3, p3, d3, gi + 3);
                    __syncwarp(FULLM);
                    fold32(s_cand[warp][0], cnt0, top0, thf0, lane);
                }
                // query 1
                if (__ballot_sync(FULLM, hit1)) {
                    const bool p0 = e0 < thf1, p1 = e1 < thf1;
                    unsigned m0 = __ballot_sync(FULLM, p0);
                    unsigned m1 = __ballot_sync(FULLM, p1);
                    PUSHM(s_cand[warp][1], cnt1, m0, p0, e0, gi);
                    PUSHM(s_cand[warp][1], cnt1, m1, p1, e1, gi + 1);
                    __syncwarp(FULLM);
                    fold32(s_cand[warp][1], cnt1, top1, thf1, lane);
                    const bool p2 = e2 < thf1, p3 = e3 < thf1;
                    unsigned m2 = __ballot_sync(FULLM, p2);
                    unsigned m3 = __ballot_sync(FULLM, p3);
                    PUSHM(s_cand[warp][1], cnt1, m2, p2, e2, gi + 2);
                    PUSHM(s_cand[warp][1], cnt1, m3, p3, e3, gi + 3);
                    __syncwarp(FULLM);
                    fold32(s_cand[warp][1], cnt1, top1, thf1, lane);
                }
            }
        }
    }
    __syncwarp(FULLM);
    if (cnt0 > 0) {
        u64 c = (lane < cnt0) ? s_cand[warp][0][lane] : INFKEY;
        c = warp_bitonic_sort(c, lane);
        top0 = warp_merge_topk(top0, c, lane);
    }
    if (cnt1 > 0) {
        u64 c = (lane < cnt1) ? s_cand[warp][1][lane] : INFKEY;
        c = warp_bitonic_sort(c, lane);
        top1 = warp_merge_topk(top1, c, lane);
    }

    g_pk[(((size_t)b * NQ + q0) * NSPLIT + split) * KS + lane]     = top0;
    g_pk[(((size_t)b * NQ + q0 + 1) * NSPLIT + split) * KS + lane] = top1;
}

// ---------------------------------------------------------------------------
// Kernel 0: feature transpose (B, C, N) -> (B, N, C).
// ---------------------------------------------------------------------------
__global__ __launch_bounds__(256)
void transpose_kernel(const float* __restrict__ feat) {
    __shared__ float t[32][33];
    const int b  = blockIdx.z;
    const int n0 = blockIdx.x * 32;
    const int c0 = blockIdx.y * 32;
    const int tx = threadIdx.x;
    const int ty = threadIdx.y;
#pragma unroll
    for (int i = 0; i < 4; i++) {
        const int c = c0 + ty + i * 8;
        t[ty + i * 8][tx] = feat[((size_t)b * CF + c) * NP + n0 + tx];
    }
    __syncthreads();
#pragma unroll
    for (int i = 0; i < 4; i++) {
        const int n = n0 + ty + i * 8;
        g_ft[((size_t)b * NP + n) * CF + c0 + tx] = t[tx][ty + i * 8];
    }
}

// ---------------------------------------------------------------------------
// Kernel 2: exact 2-way merge of sorted partial key lists -> global top-32,
// fused with gather / center / transpose / concat. One query per block.
// ---------------------------------------------------------------------------
__global__ __launch_bounds__(128)
void group_kernel(const float* __restrict__ xyz,
                  const float* __restrict__ new_xyz,
                  float* __restrict__ out) {
    const int p   = blockIdx.x;
    const int b   = blockIdx.y;
    const int tid = threadIdx.x;
    const int w    = tid >> 5;
    const int lane = tid & 31;

    __shared__ int   sidx[KS];
    __shared__ float sfeat[KS][65];

    if (w == 0) {
        const size_t kb = (((size_t)b * NQ + p) * NSPLIT) * KS;
        u64 ka = g_pk[kb + lane];
        u64 kc = g_pk[kb + KS + lane];
        u64 m  = warp_merge_topk(ka, kc, lane);   // both asc -> lowest 32 asc
        sidx[lane] = (int)(m & 0xffffffffu);
    }
    __syncthreads();

    // Stage neighbor feature rows: warp w loads rows w, w+4, ... (256B each).
    for (int s = w; s < KS; s += 4) {
        const float2* row =
            (const float2*)(g_ft + ((size_t)b * NP + sidx[s]) * CF);
        const float2 v = row[lane];
        sfeat[s][lane * 2]     = v.x;
        sfeat[s][lane * 2 + 1] = v.y;
    }
    __syncthreads();

    const int i = sidx[lane];
    for (int c = w; c < OUTC; c += 4) {
        float v;
        if (c < 3) {
            v = xyz[((size_t)b * NP + i) * 3 + c] -
                new_xyz[((size_t)b * NQ + p) * 3 + c];
        } else {
            v = sfeat[lane][c - 3];
        }
        out[(((size_t)b * OUTC + c) * NQ + p) * KS + lane] = v;
    }
}

extern "C" void kernel_launch(void* const* d_in, const int* in_sizes, int n_in,
                              void* d_out, int out_size) {
    const float* xyz     = (const float*)d_in[0];  // (B, N, 3)
    const float* new_xyz = (const float*)d_in[1];  // (B, NPOINT, 3)
    const float* feat    = (const float*)d_in[2];  // (B, C, N)
    float* out = (float*)d_out;                    // (B, 67, NPOINT, 32)

    // knn first so ncu's (-s 5 -c 1) capture lands on it.
    dim3 g1(NQ / (WPB * QPW), NSPLIT, BQ);
    knn_kernel<<<g1, WPB * 32>>>(xyz, new_xyz);

    dim3 gt(NP / 32, CF / 32, BQ);
    transpose_kernel<<<gt, dim3(32, 8)>>>(feat);

    dim3 g2(NQ, BQ);
    group_kernel<<<g2, 128>>>(xyz, new_xyz, out);
}

// round 9
// speedup vs baseline: 1.1074x; 1.1074x over previous
#include <cuda_runtime.h>

// Problem constants
#define BQ 4          // batch
#define NP 16384      // points
#define NQ 4096       // queries (npoint)
#define CF 64         // feature channels
#define KS 32         // nsample
#define OUTC (CF + 3) // 67 output channels

#define WPB 4         // warps per block (128 thr -> 2048 blocks, 7/SM, 2 waves)
#define QPW 2         // queries per warp
#define TILE 2048     // shared-memory tile of points
#define CAP 96        // per-(warp,query) candidate buffer (31 carry + 64 new)

#define FULLM 0xffffffffu
// +inf distance, max index: any real key sorts below this.
#define INFKEY 0x7f800000ffffffffULL

// Scratch: final neighbor indices (2 MB) + transposed features (16 MB).
__device__ int   g_idx[(size_t)BQ * NQ * KS];
__device__ float g_ft[(size_t)BQ * NP * CF];   // (B, N, C)

typedef unsigned long long u64;

__device__ __forceinline__ u64 pack_key(float d, int idx) {
    return ((u64)__float_as_uint(d) << 32) | (unsigned int)idx;
}

// ---- packed f32x2 helpers (sm_103a) ----
__device__ __forceinline__ u64 f2_add(u64 a, u64 b) {
    u64 r; asm("add.rn.f32x2 %0, %1, %2;" : "=l"(r) : "l"(a), "l"(b)); return r;
}
__device__ __forceinline__ u64 f2_mul(u64 a, u64 b) {
    u64 r; asm("mul.rn.f32x2 %0, %1, %2;" : "=l"(r) : "l"(a), "l"(b)); return r;
}
__device__ __forceinline__ u64 f2_fma(u64 a, u64 b, u64 c) {
    u64 r; asm("fma.rn.f32x2 %0, %1, %2, %3;" : "=l"(r) : "l"(a), "l"(b), "l"(c)); return r;
}
__device__ __forceinline__ u64 f2_bcast(float x) {
    u64 r; asm("mov.b64 %0, {%1, %1};" : "=l"(r) : "f"(x)); return r;
}
__device__ __forceinline__ void f2_unpack(u64 v, float& lo, float& hi) {
    asm("mov.b64 {%0, %1}, %2;" : "=f"(lo), "=f"(hi) : "l"(v));
}

// Warp-wide bitonic sort, ascending, one key per lane.
__device__ __forceinline__ u64 warp_bitonic_sort(u64 key, int lane) {
#pragma unroll
    for (int k = 2; k <= 32; k <<= 1) {
#pragma unroll
        for (int j = k >> 1; j > 0; j >>= 1) {
            u64 other = __shfl_xor_sync(FULLM, key, j);
            bool take_min = (((lane & k) == 0) == ((lane & j) == 0));
            bool lt = key < other;
            key = (take_min == lt) ? key : other;
        }
    }
    return key;
}

// Keep lowest 32 of (top asc-sorted) U (cand asc-sorted), result asc-sorted.
__device__ __forceinline__ u64 warp_merge_topk(u64 top, u64 cand, int lane) {
    u64 crev = __shfl_sync(FULLM, cand, 31 - lane);
    u64 v = (top < crev) ? top : crev;   // bitonic sequence = lowest 32
#pragma unroll
    for (int j = 16; j > 0; j >>= 1) {   // bitonic cleanup
        u64 other = __shfl_xor_sync(FULLM, v, j);
        bool lower = (lane & j) == 0;
        bool lt = v < other;
        v = (lower == lt) ? v : other;
    }
    return v;
}

// Fold full 32-candidate batches from buf into (top, thf).
__device__ __forceinline__ void fold32(u64* buf, int& cnt, u64& top,
                                       float& thf, int lane) {
    while (cnt >= 32) {   // take LAST 32 (order irrelevant: batch gets sorted)
        u64 c = buf[cnt - 32 + lane];
        c   = warp_bitonic_sort(c, lane);
        top = warp_merge_topk(top, c, lane);
        cnt -= 32;
        thf = __uint_as_float((unsigned)(__shfl_sync(FULLM, top, 31) >> 32));
    }
}

// Compact passing lanes of one point-group into buf via ballot.
#define PUSH(buf, cnt, pred, dval, idxval)                                     \
    do {                                                                       \
        unsigned m_ = __ballot_sync(FULLM, pred);                              \
        if (pred) (buf)[(cnt) + __popc(m_ & ltmask)] = pack_key(dval, idxval); \
        (cnt) += __popc(m_);                                                   \
    } while (0)

// ---------------------------------------------------------------------------
// Kernel 1: exact KNN, one WARP per TWO queries, single full scan.
// Tile read (3x LDS.128 / 128 pts) amortized over 256 query-points.
// Distances via packed f32x2 fma on negated SoA tiles. Strict 'd < thf'
// filter + u64 (dist,idx) bitonic top-k preserves jax.lax.top_k's stable
// tie order (ascending scan: an equal-distance later candidate loses).
// WPB=4 + 30KB smem -> 7 blocks/SM, 2048 blocks = 2 clean waves.
// ---------------------------------------------------------------------------
__global__ __launch_bounds__(WPB * 32)
void knn_kernel(const float* __restrict__ xyz,
                const float* __restrict__ new_xyz) {
    const int b    = blockIdx.y;
    const int warp = threadIdx.x >> 5;
    const int lane = threadIdx.x & 31;
    const int q0   = (blockIdx.x * WPB + warp) * QPW;
    const unsigned ltmask = (1u << lane) - 1u;

    const float* qp = new_xyz + ((size_t)b * NQ + q0) * 3;
    const u64 qxx0 = f2_bcast(qp[0]), qyy0 = f2_bcast(qp[1]), qzz0 = f2_bcast(qp[2]);
    const u64 qxx1 = f2_bcast(qp[3]), qyy1 = f2_bcast(qp[4]), qzz1 = f2_bcast(qp[5]);

    __shared__ float s_x[TILE], s_y[TILE], s_z[TILE];  // 24 KB (negated)
    __shared__ u64   s_cand[WPB][QPW][CAP];            //  6 KB

    u64 top0 = INFKEY, top1 = INFKEY;
    float thf0 = __int_as_float(0x7f800000);
    float thf1 = __int_as_float(0x7f800000);
    int cnt0 = 0, cnt1 = 0;

    for (int t0 = 0; t0 < NP; t0 += TILE) {
        __syncthreads();
        {
            const float* src = xyz + ((size_t)b * NP + t0) * 3;
#pragma unroll
            for (int k = 0; k < TILE / (WPB * 32); k++) {
                const int pt = threadIdx.x + k * (WPB * 32);
                s_x[pt] = -src[pt * 3];
                s_y[pt] = -src[pt * 3 + 1];
                s_z[pt] = -src[pt * 3 + 2];
            }
        }
        __syncthreads();

#pragma unroll 2
        for (int j = 0; j < TILE; j += 128) {
            const int o = j + 4 * lane;
            const ulonglong2 xs = *(const ulonglong2*)(s_x + o);
            const ulonglong2 ys = *(const ulonglong2*)(s_y + o);
            const ulonglong2 zs = *(const ulonglong2*)(s_z + o);

            // query 0 distances
            u64 a01, a23;
            {
                const u64 dx01 = f2_add(qxx0, xs.x), dx23 = f2_add(qxx0, xs.y);
                const u64 dy01 = f2_add(qyy0, ys.x), dy23 = f2_add(qyy0, ys.y);
                const u64 dz01 = f2_add(qzz0, zs.x), dz23 = f2_add(qzz0, zs.y);
                a01 = f2_mul(dz01, dz01);
                a23 = f2_mul(dz23, dz23);
                a01 = f2_fma(dy01, dy01, a01);
                a23 = f2_fma(dy23, dy23, a23);
                a01 = f2_fma(dx01, dx01, a01);
                a23 = f2_fma(dx23, dx23, a23);
            }
            // query 1 distances
            u64 b01, b23;
            {
                const u64 dx01 = f2_add(qxx1, xs.x), dx23 = f2_add(qxx1, xs.y);
                const u64 dy01 = f2_add(qyy1, ys.x), dy23 = f2_add(qyy1, ys.y);
                const u64 dz01 = f2_add(qzz1, zs.x), dz23 = f2_add(qzz1, zs.y);
                b01 = f2_mul(dz01, dz01);
                b23 = f2_mul(dz23, dz23);
                b01 = f2_fma(dy01, dy01, b01);
                b23 = f2_fma(dy23, dy23, b23);
                b01 = f2_fma(dx01, dx01, b01);
                b23 = f2_fma(dx23, dx23, b23);
            }

            float d0, d1, d2, d3, e0, e1, e2, e3;
            f2_unpack(a01, d0, d1);  f2_unpack(a23, d2, d3);
            f2_unpack(b01, e0, e1);  f2_unpack(b23, e2, e3);

            const bool hit0 = fminf(fminf(d0, d1), fminf(d2, d3)) < thf0;
            const bool hit1 = fminf(fminf(e0, e1), fminf(e2, e3)) < thf1;
            if (__any_sync(FULLM, hit0 | hit1)) {
                const int gi = t0 + j + 4 * lane;
                if (__ballot_sync(FULLM, hit0)) {
                    PUSH(s_cand[warp][0], cnt0, d0 < thf0, d0, gi);
                    PUSH(s_cand[warp][0], cnt0, d1 < thf0, d1, gi + 1);
                    __syncwarp(FULLM);
                    fold32(s_cand[warp][0], cnt0, top0, thf0, lane);
                    PUSH(s_cand[warp][0], cnt0, d2 < thf0, d2, gi + 2);
                    PUSH(s_cand[warp][0], cnt0, d3 < thf0, d3, gi + 3);
                    __syncwarp(FULLM);
                    fold32(s_cand[warp][0], cnt0, top0, thf0, lane);
                }
                if (__ballot_sync(FULLM, hit1)) {
                    PUSH(s_cand[warp][1], cnt1, e0 < thf1, e0, gi);
                    PUSH(s_cand[warp][1], cnt1, e1 < thf1, e1, gi + 1);
                    __syncwarp(FULLM);
                    fold32(s_cand[warp][1], cnt1, top1, thf1, lane);
                    PUSH(s_cand[warp][1], cnt1, e2 < thf1, e2, gi + 2);
                    PUSH(s_cand[warp][1], cnt1, e3 < thf1, e3, gi + 3);
                    __syncwarp(FULLM);
                    fold32(s_cand[warp][1], cnt1, top1, thf1, lane);
                }
            }
        }
    }
    __syncwarp(FULLM);
    if (cnt0 > 0) {
        u64 c = (lane < cnt0) ? s_cand[warp][0][lane] : INFKEY;
        c = warp_bitonic_sort(c, lane);
        top0 = warp_merge_topk(top0, c, lane);
    }
    if (cnt1 > 0) {
        u64 c = (lane < cnt1) ? s_cand[warp][1][lane] : INFKEY;
        c = warp_bitonic_sort(c, lane);
        top1 = warp_merge_topk(top1, c, lane);
    }

    // tops are ascending by (dist, idx) -> slot order matches top_k output.
    g_idx[((size_t)b * NQ + q0) * KS + lane]     = (int)(top0 & 0xffffffffu);
    g_idx[((size_t)b * NQ + q0 + 1) * KS + lane] = (int)(top1 & 0xffffffffu);
}

// ---------------------------------------------------------------------------
// Kernel 0: feature transpose (B, C, N) -> (B, N, C).
// ---------------------------------------------------------------------------
__global__ __launch_bounds__(256)
void transpose_kernel(const float* __restrict__ feat) {
    __shared__ float t[32][33];
    const int b  = blockIdx.z;
    const int n0 = blockIdx.x * 32;
    const int c0 = blockIdx.y * 32;
    const int tx = threadIdx.x;
    const int ty = threadIdx.y;
#pragma unroll
    for (int i = 0; i < 4; i++) {
        const int c = c0 + ty + i * 8;
        t[ty + i * 8][tx] = feat[((size_t)b * CF + c) * NP + n0 + tx];
    }
    __syncthreads();
#pragma unroll
    for (int i = 0; i < 4; i++) {
        const int n = n0 + ty + i * 8;
        g_ft[((size_t)b * NP + n) * CF + c0 + tx] = t[tx][ty + i * 8];
    }
}

// ---------------------------------------------------------------------------
// Kernel 2: gather / center / transpose / concat. One query per block.
// ---------------------------------------------------------------------------
__global__ __launch_bounds__(128)
void group_kernel(const float* __restrict__ xyz,
                  const float* __restrict__ new_xyz,
                  float* __restrict__ out) {
    const int p   = blockIdx.x;
    const int b   = blockIdx.y;
    const int tid = threadIdx.x;
    const int w    = tid >> 5;
    const int lane = tid & 31;

    __shared__ int   sidx[KS];
    __shared__ float sfeat[KS][65];

    if (tid < KS) sidx[tid] = g_idx[((size_t)b * NQ + p) * KS + tid];
    __syncthreads();

    // Stage neighbor feature rows: warp w loads rows w, w+4, ... (256B each).
    for (int s = w; s < KS; s += 4) {
        const float2* row =
            (const float2*)(g_ft + ((size_t)b * NP + sidx[s]) * CF);
        const float2 v = row[lane];
        sfeat[s][lane * 2]     = v.x;
        sfeat[s][lane * 2 + 1] = v.y;
    }
    __syncthreads();

    const int i = sidx[lane];
    for (int c = w; c < OUTC; c += 4) {
        float v;
        if (c < 3) {
            v = xyz[((size_t)b * NP + i) * 3 + c] -
                new_xyz[((size_t)b * NQ + p) * 3 + c];
        } else {
            v = sfeat[lane][c - 3];
        }
        out[(((size_t)b * OUTC + c) * NQ + p) * KS + lane] = v;
    }
}

extern "C" void kernel_launch(void* const* d_in, const int* in_sizes, int n_in,
                              void* d_out, int out_size) {
    const float* xyz     = (const float*)d_in[0];  // (B, N, 3)
    const float* new_xyz = (const float*)d_in[1];  // (B, NPOINT, 3)
    const float* feat    = (const float*)d_in[2];  // (B, C, N)
    float* out = (float*)d_out;                    // (B, 67, NPOINT, 32)

    // knn first so ncu's (-s 5 -c 1) capture lands on it.
    dim3 g1(NQ / (WPB * QPW), BQ);
    knn_kernel<<<g1, WPB * 32>>>(xyz, new_xyz);

    dim3 gt(NP / 32, CF / 32, BQ);
    transpose_kernel<<<gt, dim3(32, 8)>>>(feat);

    dim3 g2(NQ, BQ);
    group_kernel<<<g2, 128>>>(xyz, new_xyz, out);
}

// round 11
// speedup vs baseline: 1.1364x; 1.0261x over previous
#include <cuda_runtime.h>

// Problem constants
#define BQ 4          // batch
#define NP 16384      // points
#define NQ 4096       // queries (npoint)
#define CF 64         // feature channels
#define KS 32         // nsample
#define OUTC (CF + 3) // 67 output channels

#define WPB 8         // warps per block
#define QPW 2         // queries per warp
#define TILE 2048     // shared-memory tile of points
#define CAP 160       // per-(warp,query) candidate buffer

#define KNN_BX (NQ / (WPB * QPW))          // 256 knn blocks per batch
#define TP_BX  ((NP / 32) * (CF / 32))     // 1024 transpose blocks per batch

#define FULLM 0xffffffffu
// +inf distance, max index: any real key sorts below this.
#define INFKEY 0x7f800000ffffffffULL

// Scratch: final neighbor indices (2 MB) + transposed features (16 MB).
__device__ int   g_idx[(size_t)BQ * NQ * KS];
__device__ float g_ft[(size_t)BQ * NP * CF];   // (B, N, C)

typedef unsigned long long u64;

__device__ __forceinline__ u64 pack_key(float d, int idx) {
    return ((u64)__float_as_uint(d) << 32) | (unsigned int)idx;
}

// ---- packed f32x2 helpers (sm_103a) ----
__device__ __forceinline__ u64 f2_add(u64 a, u64 b) {
    u64 r; asm("add.rn.f32x2 %0, %1, %2;" : "=l"(r) : "l"(a), "l"(b)); return r;
}
__device__ __forceinline__ u64 f2_mul(u64 a, u64 b) {
    u64 r; asm("mul.rn.f32x2 %0, %1, %2;" : "=l"(r) : "l"(a), "l"(b)); return r;
}
__device__ __forceinline__ u64 f2_fma(u64 a, u64 b, u64 c) {
    u64 r; asm("fma.rn.f32x2 %0, %1, %2, %3;" : "=l"(r) : "l"(a), "l"(b), "l"(c)); return r;
}
__device__ __forceinline__ u64 f2_bcast(float x) {
    u64 r; asm("mov.b64 %0, {%1, %1};" : "=l"(r) : "f"(x)); return r;
}
__device__ __forceinline__ void f2_unpack(u64 v, float& lo, float& hi) {
    asm("mov.b64 {%0, %1}, %2;" : "=f"(lo), "=f"(hi) : "l"(v));
}

// Warp-wide bitonic sort, ascending, one key per lane.
__device__ __forceinline__ u64 warp_bitonic_sort(u64 key, int lane) {
#pragma unroll
    for (int k = 2; k <= 32; k <<= 1) {
#pragma unroll
        for (int j = k >> 1; j > 0; j >>= 1) {
            u64 other = __shfl_xor_sync(FULLM, key, j);
            bool take_min = (((lane & k) == 0) == ((lane & j) == 0));
            bool lt = key < other;
            key = (take_min == lt) ? key : other;
        }
    }
    return key;
}

// Keep lowest 32 of (top asc-sorted) U (cand asc-sorted), result asc-sorted.
__device__ __forceinline__ u64 warp_merge_topk(u64 top, u64 cand, int lane) {
    u64 crev = __shfl_sync(FULLM, cand, 31 - lane);
    u64 v = (top < crev) ? top : crev;   // bitonic sequence = lowest 32
#pragma unroll
    for (int j = 16; j > 0; j >>= 1) {   // bitonic cleanup
        u64 other = __shfl_xor_sync(FULLM, v, j);
        bool lower = (lane & j) == 0;
        bool lt = v < other;
        v = (lower == lt) ? v : other;
    }
    return v;
}

// Fold full 32-candidate batches from buf into (top, thf).
__device__ __forceinline__ void fold32(u64* buf, int& cnt, u64& top,
                                       float& thf, int lane) {
    while (cnt >= 32) {   // take LAST 32 (order irrelevant: batch gets sorted)
        u64 c = buf[cnt - 32 + lane];
        c   = warp_bitonic_sort(c, lane);
        top = warp_merge_topk(top, c, lane);
        cnt -= 32;
        thf = __uint_as_float((unsigned)(__shfl_sync(FULLM, top, 31) >> 32));
    }
}

// Compact passing lanes of one point-group into buf via ballot.
#define PUSH(buf, cnt, pred, dval, idxval)                                     \
    do {                                                                       \
        unsigned m_ = __ballot_sync(FULLM, pred);                              \
        if (pred) (buf)[(cnt) + __popc(m_ & ltmask)] = pack_key(dval, idxval); \
        (cnt) += __popc(m_);                                                   \
    } while (0)

// ---------------------------------------------------------------------------
// Kernel 1 (fused): blockIdx.x <  KNN_BX -> exact KNN (R7 body, proven).
//                   blockIdx.x >= KNN_BX -> feature transpose (B,C,N)->(B,N,C).
// The 4096 short transpose blocks backfill the idle tail of the knn wave
// schedule, hiding the transpose entirely. smem for the transpose tile is
// overlaid on the knn point tile (whole block takes one branch).
// ---------------------------------------------------------------------------
__global__ __launch_bounds__(WPB * 32)
void knn_tp_kernel(const float* __restrict__ xyz,
                   const float* __restrict__ new_xyz,
                   const float* __restrict__ feat) {
    __shared__ float s_x[TILE], s_y[TILE], s_z[TILE];  // 24 KB (negated)
    __shared__ u64   s_cand[WPB][QPW][CAP];            // 20 KB

    const int b = blockIdx.y;

    if (blockIdx.x >= KNN_BX) {
        // ---- transpose path ----
        float (*t)[33] = (float(*)[33])s_x;   // 32x33 floats, fits in s_x
        const int tb = blockIdx.x - KNN_BX;
        const int n0 = (tb & (NP / 32 - 1)) * 32;
        const int c0 = (tb >> 9) * 32;
        const int tx = threadIdx.x & 31;
        const int ty = threadIdx.x >> 5;      // 0..7
#pragma unroll
        for (int i = 0; i < 4; i++) {
            const int c = c0 + ty + i * 8;
            t[ty + i * 8][tx] = feat[((size_t)b * CF + c) * NP + n0 + tx];
        }
        __syncthreads();
#pragma unroll
        for (int i = 0; i < 4; i++) {
            const int n = n0 + ty + i * 8;
            g_ft[((size_t)b * NP + n) * CF + c0 + tx] = t[tx][ty + i * 8];
        }
        return;
    }

    // ---- knn path (R7 body) ----
    const int warp = threadIdx.x >> 5;
    const int lane = threadIdx.x & 31;
    const int q0   = (blockIdx.x * WPB + warp) * QPW;
    const unsigned ltmask = (1u << lane) - 1u;

    const float* qp = new_xyz + ((size_t)b * NQ + q0) * 3;
    const u64 qxx0 = f2_bcast(qp[0]), qyy0 = f2_bcast(qp[1]), qzz0 = f2_bcast(qp[2]);
    const u64 qxx1 = f2_bcast(qp[3]), qyy1 = f2_bcast(qp[4]), qzz1 = f2_bcast(qp[5]);

    u64 top0 = INFKEY, top1 = INFKEY;
    float thf0 = __int_as_float(0x7f800000);
    float thf1 = __int_as_float(0x7f800000);
    int cnt0 = 0, cnt1 = 0;

    for (int t0 = 0; t0 < NP; t0 += TILE) {
        __syncthreads();
        {
            const float* src = xyz + ((size_t)b * NP + t0) * 3;
#pragma unroll
            for (int k = 0; k < TILE / (WPB * 32); k++) {
                const int pt = threadIdx.x + k * (WPB * 32);
                s_x[pt] = -src[pt * 3];
                s_y[pt] = -src[pt * 3 + 1];
                s_z[pt] = -src[pt * 3 + 2];
            }
        }
        __syncthreads();

#pragma unroll 2
        for (int j = 0; j < TILE; j += 128) {
            const int o = j + 4 * lane;
            const ulonglong2 xs = *(const ulonglong2*)(s_x + o);
            const ulonglong2 ys = *(const ulonglong2*)(s_y + o);
            const ulonglong2 zs = *(const ulonglong2*)(s_z + o);

            // query 0 distances
            u64 a01, a23;
            {
                const u64 dx01 = f2_add(qxx0, xs.x), dx23 = f2_add(qxx0, xs.y);
                const u64 dy01 = f2_add(qyy0, ys.x), dy23 = f2_add(qyy0, ys.y);
                const u64 dz01 = f2_add(qzz0, zs.x), dz23 = f2_add(qzz0, zs.y);
                a01 = f2_mul(dz01, dz01);
                a23 = f2_mul(dz23, dz23);
                a01 = f2_fma(dy01, dy01, a01);
                a23 = f2_fma(dy23, dy23, a23);
                a01 = f2_fma(dx01, dx01, a01);
                a23 = f2_fma(dx23, dx23, a23);
            }
            // query 1 distances
            u64 b01, b23;
            {
                const u64 dx01 = f2_add(qxx1, xs.x), dx23 = f2_add(qxx1, xs.y);
                const u64 dy01 = f2_add(qyy1, ys.x), dy23 = f2_add(qyy1, ys.y);
                const u64 dz01 = f2_add(qzz1, zs.x), dz23 = f2_add(qzz1, zs.y);
                b01 = f2_mul(dz01, dz01);
                b23 = f2_mul(dz23, dz23);
                b01 = f2_fma(dy01, dy01, b01);
                b23 = f2_fma(dy23, dy23, b23);
                b01 = f2_fma(dx01, dx01, b01);
                b23 = f2_fma(dx23, dx23, b23);
            }

            float d0, d1, d2, d3, e0, e1, e2, e3;
            f2_unpack(a01, d0, d1);  f2_unpack(a23, d2, d3);
            f2_unpack(b01, e0, e1);  f2_unpack(b23, e2, e3);

            const bool hit0 = fminf(fminf(d0, d1), fminf(d2, d3)) < thf0;
            const bool hit1 = fminf(fminf(e0, e1), fminf(e2, e3)) < thf1;
            if (__any_sync(FULLM, hit0 | hit1)) {
                const int gi = t0 + o;
                PUSH(s_cand[warp][0], cnt0, d0 < thf0, d0, gi);
                PUSH(s_cand[warp][0], cnt0, d1 < thf0, d1, gi + 1);
                PUSH(s_cand[warp][0], cnt0, d2 < thf0, d2, gi + 2);
                PUSH(s_cand[warp][0], cnt0, d3 < thf0, d3, gi + 3);
                PUSH(s_cand[warp][1], cnt1, e0 < thf1, e0, gi);
                PUSH(s_cand[warp][1], cnt1, e1 < thf1, e1, gi + 1);
                PUSH(s_cand[warp][1], cnt1, e2 < thf1, e2, gi + 2);
                PUSH(s_cand[warp][1], cnt1, e3 < thf1, e3, gi + 3);
                __syncwarp(FULLM);
                fold32(s_cand[warp][0], cnt0, top0, thf0, lane);
                fold32(s_cand[warp][1], cnt1, top1, thf1, lane);
            }
        }
    }
    __syncwarp(FULLM);
    if (cnt0 > 0) {
        u64 c = (lane < cnt0) ? s_cand[warp][0][lane] : INFKEY;
        c = warp_bitonic_sort(c, lane);
        top0 = warp_merge_topk(top0, c, lane);
    }
    if (cnt1 > 0) {
        u64 c = (lane < cnt1) ? s_cand[warp][1][lane] : INFKEY;
        c = warp_bitonic_sort(c, lane);
        top1 = warp_merge_topk(top1, c, lane);
    }

    // tops are ascending by (dist, idx) -> slot order matches top_k output.
    g_idx[((size_t)b * NQ + q0) * KS + lane]     = (int)(top0 & 0xffffffffu);
    g_idx[((size_t)b * NQ + q0 + 1) * KS + lane] = (int)(top1 & 0xffffffffu);
}

// ---------------------------------------------------------------------------
// Kernel 2: gather / center / transpose / concat. TWO queries per 256-thread
// block (warps 0-3 -> query p0, warps 4-7 -> p1). Coalesced 256B feature-row
// reads -> smem -> conflict-free reads -> coalesced 128B output stores.
// ---------------------------------------------------------------------------
__global__ __launch_bounds__(256)
void group_kernel(const float* __restrict__ xyz,
                  const float* __restrict__ new_xyz,
                  float* __restrict__ out) {
    const int b    = blockIdx.y;
    const int half = threadIdx.x >> 7;               // 0 or 1
    const int p    = blockIdx.x * 2 + half;
    const int t    = threadIdx.x & 127;
    const int w    = t >> 5;
    const int lane = t & 31;

    __shared__ int   sidx[2][KS];
    __shared__ float sfeat[2][KS][65];

    if (t < KS) sidx[half][t] = g_idx[((size_t)b * NQ + p) * KS + t];
    __syncthreads();

    // Stage neighbor feature rows: warp w loads rows w, w+4, ... (256B each).
    for (int s = w; s < KS; s += 4) {
        const float2* row =
            (const float2*)(g_ft + ((size_t)b * NP + sidx[half][s]) * CF);
        const float2 v = row[lane];
        sfeat[half][s][lane * 2]     = v.x;
        sfeat[half][s][lane * 2 + 1] = v.y;
    }
    __syncthreads();

    const int i = sidx[half][lane];
    for (int c = w; c < OUTC; c += 4) {
        float v;
        if (c < 3) {
            v = xyz[((size_t)b * NP + i) * 3 + c] -
                new_xyz[((size_t)b * NQ + p) * 3 + c];
        } else {
            v = sfeat[half][lane][c - 3];
        }
        out[(((size_t)b * OUTC + c) * NQ + p) * KS + lane] = v;
    }
}

extern "C" void kernel_launch(void* const* d_in, const int* in_sizes, int n_in,
                              void* d_out, int out_size) {
    const float* xyz     = (const float*)d_in[0];  // (B, N, 3)
    const float* new_xyz = (const float*)d_in[1];  // (B, NPOINT, 3)
    const float* feat    = (const float*)d_in[2];  // (B, C, N)
    float* out = (float*)d_out;                    // (B, 67, NPOINT, 32)

    // Fused knn + transpose: knn blocks first (long), transpose blocks
    // backfill the wave tail.
    dim3 g1(KNN_BX + TP_BX, BQ);
    knn_tp_kernel<<<g1, WPB * 32>>>(xyz, new_xyz, feat);

    dim3 g2(NQ / 2, BQ);
    group_kernel<<<g2, 256>>>(xyz, new_xyz, out);
}

// round 14
// speedup vs baseline: 1.1877x; 1.0451x over previous
#include <cuda_runtime.h>

// Problem constants
#define BQ 4          // batch
#define NP 16384      // points
#define NQ 4096       // queries (npoint)
#define CF 64         // feature channels
#define KS 32         // nsample
#define OUTC (CF + 3) // 67 output channels

#define WPB 8         // warps per block
#define QPW 2         // queries per warp
#define TILE 2048     // shared-memory tile of points
#define CAP 160       // per-(warp,query) candidate buffer

#define KNN_BX (NQ / (WPB * QPW))          // 256 knn blocks per batch
#define TP_BX  ((NP / 32) * (CF / 32))     // 1024 transpose blocks per batch

#define FULLM 0xffffffffu
// +inf distance, max index: any real key sorts below this.
#define INFKEY 0x7f800000ffffffffULL

// Scratch: final neighbor indices (2 MB) + transposed features (16 MB).
__device__ int   g_idx[(size_t)BQ * NQ * KS];
__device__ float g_ft[(size_t)BQ * NP * CF];   // (B, N, C)

typedef unsigned long long u64;

__device__ __forceinline__ u64 pack_key(float d, int idx) {
    return ((u64)__float_as_uint(d) << 32) | (unsigned int)idx;
}

// ---- packed f32x2 helpers (sm_103a) ----
__device__ __forceinline__ u64 f2_add(u64 a, u64 b) {
    u64 r; asm("add.rn.f32x2 %0, %1, %2;" : "=l"(r) : "l"(a), "l"(b)); return r;
}
__device__ __forceinline__ u64 f2_mul(u64 a, u64 b) {
    u64 r; asm("mul.rn.f32x2 %0, %1, %2;" : "=l"(r) : "l"(a), "l"(b)); return r;
}
__device__ __forceinline__ u64 f2_fma(u64 a, u64 b, u64 c) {
    u64 r; asm("fma.rn.f32x2 %0, %1, %2, %3;" : "=l"(r) : "l"(a), "l"(b), "l"(c)); return r;
}
__device__ __forceinline__ u64 f2_bcast(float x) {
    u64 r; asm("mov.b64 %0, {%1, %1};" : "=l"(r) : "f"(x)); return r;
}
__device__ __forceinline__ void f2_unpack(u64 v, float& lo, float& hi) {
    asm("mov.b64 {%0, %1}, %2;" : "=f"(lo), "=f"(hi) : "l"(v));
}

// Warp-wide bitonic sort, ascending, one key per lane.
__device__ __forceinline__ u64 warp_bitonic_sort(u64 key, int lane) {
#pragma unroll
    for (int k = 2; k <= 32; k <<= 1) {
#pragma unroll
        for (int j = k >> 1; j > 0; j >>= 1) {
            u64 other = __shfl_xor_sync(FULLM, key, j);
            bool take_min = (((lane & k) == 0) == ((lane & j) == 0));
            bool lt = key < other;
            key = (take_min == lt) ? key : other;
        }
    }
    return key;
}

// Keep lowest 32 of (top asc-sorted) U (cand asc-sorted), result asc-sorted.
__device__ __forceinline__ u64 warp_merge_topk(u64 top, u64 cand, int lane) {
    u64 crev = __shfl_sync(FULLM, cand, 31 - lane);
    u64 v = (top < crev) ? top : crev;   // bitonic sequence = lowest 32
#pragma unroll
    for (int j = 16; j > 0; j >>= 1) {   // bitonic cleanup
        u64 other = __shfl_xor_sync(FULLM, v, j);
        bool lower = (lane & j) == 0;
        bool lt = v < other;
        v = (lower == lt) ? v : other;
    }
    return v;
}

// Fold full 32-candidate batches from buf into (top, thf).
__device__ __forceinline__ void fold32(u64* buf, int& cnt, u64& top,
                                       float& thf, int lane) {
    while (cnt >= 32) {   // take LAST 32 (order irrelevant: batch gets sorted)
        u64 c = buf[cnt - 32 + lane];
        c   = warp_bitonic_sort(c, lane);
        top = warp_merge_topk(top, c, lane);
        cnt -= 32;
        thf = __uint_as_float((unsigned)(__shfl_sync(FULLM, top, 31) >> 32));
    }
}

// Compact passing lanes of one point-group into buf via ballot.
#define PUSH(buf, cnt, pred, dval, idxval)                                     \
    do {                                                                       \
        unsigned m_ = __ballot_sync(FULLM, pred);                              \
        if (pred) (buf)[(cnt) + __popc(m_ & ltmask)] = pack_key(dval, idxval); \
        (cnt) += __popc(m_);                                                   \
    } while (0)

// ---------------------------------------------------------------------------
// Kernel 1 (fused): blockIdx.x <  KNN_BX -> exact KNN.
//                   blockIdx.x >= KNN_BX -> feature transpose (B,C,N)->(B,N,C).
// The 4096 short transpose blocks backfill the idle tail of the knn wave
// schedule. Slow path is PER-QUERY gated: in the converged phase most entries
// are one-sided, so the other query's 4 ballots+pushes+fold are skipped.
// ---------------------------------------------------------------------------
__global__ __launch_bounds__(WPB * 32)
void knn_tp_kernel(const float* __restrict__ xyz,
                   const float* __restrict__ new_xyz,
                   const float* __restrict__ feat) {
    __shared__ float s_x[TILE], s_y[TILE], s_z[TILE];  // 24 KB (negated)
    __shared__ u64   s_cand[WPB][QPW][CAP];            // 20 KB

    const int b = blockIdx.y;

    if (blockIdx.x >= KNN_BX) {
        // ---- transpose path ----
        float (*t)[33] = (float(*)[33])s_x;   // 32x33 floats, fits in s_x
        const int tb = blockIdx.x - KNN_BX;
        const int n0 = (tb & (NP / 32 - 1)) * 32;
        const int c0 = (tb >> 9) * 32;
        const int tx = threadIdx.x & 31;
        const int ty = threadIdx.x >> 5;      // 0..7
#pragma unroll
        for (int i = 0; i < 4; i++) {
            const int c = c0 + ty + i * 8;
            t[ty + i * 8][tx] = feat[((size_t)b * CF + c) * NP + n0 + tx];
        }
        __syncthreads();
#pragma unroll
        for (int i = 0; i < 4; i++) {
            const int n = n0 + ty + i * 8;
            g_ft[((size_t)b * NP + n) * CF + c0 + tx] = t[tx][ty + i * 8];
        }
        return;
    }

    // ---- knn path ----
    const int warp = threadIdx.x >> 5;
    const int lane = threadIdx.x & 31;
    const int q0   = (blockIdx.x * WPB + warp) * QPW;
    const unsigned ltmask = (1u << lane) - 1u;

    const float* qp = new_xyz + ((size_t)b * NQ + q0) * 3;
    const u64 qxx0 = f2_bcast(qp[0]), qyy0 = f2_bcast(qp[1]), qzz0 = f2_bcast(qp[2]);
    const u64 qxx1 = f2_bcast(qp[3]), qyy1 = f2_bcast(qp[4]), qzz1 = f2_bcast(qp[5]);

    u64 top0 = INFKEY, top1 = INFKEY;
    float thf0 = __int_as_float(0x7f800000);
    float thf1 = __int_as_float(0x7f800000);
    int cnt0 = 0, cnt1 = 0;

    for (int t0 = 0; t0 < NP; t0 += TILE) {
        __syncthreads();
        {
            const float* src = xyz + ((size_t)b * NP + t0) * 3;
#pragma unroll
            for (int k = 0; k < TILE / (WPB * 32); k++) {
                const int pt = threadIdx.x + k * (WPB * 32);
                s_x[pt] = -src[pt * 3];
                s_y[pt] = -src[pt * 3 + 1];
                s_z[pt] = -src[pt * 3 + 2];
            }
        }
        __syncthreads();

#pragma unroll 2
        for (int j = 0; j < TILE; j += 128) {
            const int o = j + 4 * lane;
            const ulonglong2 xs = *(const ulonglong2*)(s_x + o);
            const ulonglong2 ys = *(const ulonglong2*)(s_y + o);
            const ulonglong2 zs = *(const ulonglong2*)(s_z + o);

            // query 0 distances
            u64 a01, a23;
            {
                const u64 dx01 = f2_add(qxx0, xs.x), dx23 = f2_add(qxx0, xs.y);
                const u64 dy01 = f2_add(qyy0, ys.x), dy23 = f2_add(qyy0, ys.y);
                const u64 dz01 = f2_add(qzz0, zs.x), dz23 = f2_add(qzz0, zs.y);
                a01 = f2_mul(dz01, dz01);
                a23 = f2_mul(dz23, dz23);
                a01 = f2_fma(dy01, dy01, a01);
                a23 = f2_fma(dy23, dy23, a23);
                a01 = f2_fma(dx01, dx01, a01);
                a23 = f2_fma(dx23, dx23, a23);
            }
            // query 1 distances
            u64 b01, b23;
            {
                const u64 dx01 = f2_add(qxx1, xs.x), dx23 = f2_add(qxx1, xs.y);
                const u64 dy01 = f2_add(qyy1, ys.x), dy23 = f2_add(qyy1, ys.y);
                const u64 dz01 = f2_add(qzz1, zs.x), dz23 = f2_add(qzz1, zs.y);
                b01 = f2_mul(dz01, dz01);
                b23 = f2_mul(dz23, dz23);
                b01 = f2_fma(dy01, dy01, b01);
                b23 = f2_fma(dy23, dy23, b23);
                b01 = f2_fma(dx01, dx01, b01);
                b23 = f2_fma(dx23, dx23, b23);
            }

            float d0, d1, d2, d3, e0, e1, e2, e3;
            f2_unpack(a01, d0, d1);  f2_unpack(a23, d2, d3);
            f2_unpack(b01, e0, e1);  f2_unpack(b23, e2, e3);

            const bool hit0 = fminf(fminf(d0, d1), fminf(d2, d3)) < thf0;
            const bool hit1 = fminf(fminf(e0, e1), fminf(e2, e3)) < thf1;
            if (__any_sync(FULLM, hit0 | hit1)) {
                const int gi = t0 + o;
                // per-query gates: skip the whole block when one-sided
                if (__ballot_sync(FULLM, hit0)) {
                    PUSH(s_cand[warp][0], cnt0, d0 < thf0, d0, gi);
                    PUSH(s_cand[warp][0], cnt0, d1 < thf0, d1, gi + 1);
                    PUSH(s_cand[warp][0], cnt0, d2 < thf0, d2, gi + 2);
                    PUSH(s_cand[warp][0], cnt0, d3 < thf0, d3, gi + 3);
                    __syncwarp(FULLM);
                    fold32(s_cand[warp][0], cnt0, top0, thf0, lane);
                }
                if (__ballot_sync(FULLM, hit1)) {
                    PUSH(s_cand[warp][1], cnt1, e0 < thf1, e0, gi);
                    PUSH(s_cand[warp][1], cnt1, e1 < thf1, e1, gi + 1);
                    PUSH(s_cand[warp][1], cnt1, e2 < thf1, e2, gi + 2);
                    PUSH(s_cand[warp][1], cnt1, e3 < thf1, e3, gi + 3);
                    __syncwarp(FULLM);
                    fold32(s_cand[warp][1], cnt1, top1, thf1, lane);
                }
            }
        }
    }
    __syncwarp(FULLM);
    if (cnt0 > 0) {
        u64 c = (lane < cnt0) ? s_cand[warp][0][lane] : INFKEY;
        c = warp_bitonic_sort(c, lane);
        top0 = warp_merge_topk(top0, c, lane);
    }
    if (cnt1 > 0) {
        u64 c = (lane < cnt1) ? s_cand[warp][1][lane] : INFKEY;
        c = warp_bitonic_sort(c, lane);
        top1 = warp_merge_topk(top1, c, lane);
    }

    // tops are ascending by (dist, idx) -> slot order matches top_k output.
    g_idx[((size_t)b * NQ + q0) * KS + lane]     = (int)(top0 & 0xffffffffu);
    g_idx[((size_t)b * NQ + q0 + 1) * KS + lane] = (int)(top1 & 0xffffffffu);
}

// ---------------------------------------------------------------------------
// Kernel 2: gather / center / transpose / concat. TWO queries per 256-thread
// block (warps 0-3 -> query p0, warps 4-7 -> p1). Coalesced 256B feature-row
// reads -> smem -> conflict-free reads -> coalesced 128B output stores.
// ---------------------------------------------------------------------------
__global__ __launch_bounds__(256)
void group_kernel(const float* __restrict__ xyz,
                  const float* __restrict__ new_xyz,
                  float* __restrict__ out) {
    const int b    = blockIdx.y;
    const int half = threadIdx.x >> 7;               // 0 or 1
    const int p    = blockIdx.x * 2 + half;
    const int t    = threadIdx.x & 127;
    const int w    = t >> 5;
    const int lane = t & 31;

    __shared__ int   sidx[2][KS];
    __shared__ float sfeat[2][KS][65];

    if (t < KS) sidx[half][t] = g_idx[((size_t)b * NQ + p) * KS + t];
    __syncthreads();

    // Stage neighbor feature rows: warp w loads rows w, w+4, ... (256B each).
    for (int s = w; s < KS; s += 4) {
        const float2* row =
            (const float2*)(g_ft + ((size_t)b * NP + sidx[half][s]) * CF);
        const float2 v = row[lane];
        sfeat[half][s][lane * 2]     = v.x;
        sfeat[half][s][lane * 2 + 1] = v.y;
    }
    __syncthreads();

    const int i = sidx[half][lane];
    for (int c = w; c < OUTC; c += 4) {
        float v;
        if (c < 3) {
            v = xyz[((size_t)b * NP + i) * 3 + c] -
                new_xyz[((size_t)b * NQ + p) * 3 + c];
        } else {
            v = sfeat[half][lane][c - 3];
        }
        out[(((size_t)b * OUTC + c) * NQ + p) * KS + lane] = v;
    }
}

extern "C" void kernel_launch(void* const* d_in, const int* in_sizes, int n_in,
                              void* d_out, int out_size) {
    const float* xyz     = (const float*)d_in[0];  // (B, N, 3)
    const float* new_xyz = (const float*)d_in[1];  // (B, NPOINT, 3)
    const float* feat    = (const float*)d_in[2];  // (B, C, N)
    float* out = (float*)d_out;                    // (B, 67, NPOINT, 32)

    // Fused knn + transpose: knn blocks first (long), transpose blocks
    // backfill the wave tail.
    dim3 g1(KNN_BX + TP_BX, BQ);
    knn_tp_kernel<<<g1, WPB * 32>>>(xyz, new_xyz, feat);

    dim3 g2(NQ / 2, BQ);
    group_kernel<<<g2, 256>>>(xyz, new_xyz, out);
}

// round 16
// speedup vs baseline: 1.2131x; 1.0214x over previous
#include <cuda_runtime.h>

// Problem constants
#define BQ 4          // batch
#define NP 16384      // points
#define NQ 4096       // queries (npoint)
#define CF 64         // feature channels
#define KS 32         // nsample
#define OUTC (CF + 3) // 67 output channels

#define WPB 8         // warps per block
#define QPW 2         // queries per warp
#define TILE 2048     // shared-memory tile of points
#define CAP 160       // per-(warp,query) candidate buffer

#define KNN_BX (NQ / (WPB * QPW))          // 256 knn blocks per batch
#define TP_BX  ((NP / 32) * (CF / 32))     // 1024 transpose blocks per batch

#define FULLM 0xffffffffu
// +inf distance, max index: any real key sorts below this.
#define INFKEY 0x7f800000ffffffffULL

// Scratch: final neighbor indices (2 MB) + transposed features (16 MB).
__device__ int   g_idx[(size_t)BQ * NQ * KS];
__device__ float g_ft[(size_t)BQ * NP * CF];   // (B, N, C)

typedef unsigned long long u64;

__device__ __forceinline__ u64 pack_key(float d, int idx) {
    return ((u64)__float_as_uint(d) << 32) | (unsigned int)idx;
}

// ---- packed f32x2 helpers (sm_103a) ----
__device__ __forceinline__ u64 f2_add(u64 a, u64 b) {
    u64 r; asm("add.rn.f32x2 %0, %1, %2;" : "=l"(r) : "l"(a), "l"(b)); return r;
}
__device__ __forceinline__ u64 f2_mul(u64 a, u64 b) {
    u64 r; asm("mul.rn.f32x2 %0, %1, %2;" : "=l"(r) : "l"(a), "l"(b)); return r;
}
__device__ __forceinline__ u64 f2_fma(u64 a, u64 b, u64 c) {
    u64 r; asm("fma.rn.f32x2 %0, %1, %2, %3;" : "=l"(r) : "l"(a), "l"(b), "l"(c)); return r;
}
__device__ __forceinline__ u64 f2_bcast(float x) {
    u64 r; asm("mov.b64 %0, {%1, %1};" : "=l"(r) : "f"(x)); return r;
}
__device__ __forceinline__ void f2_unpack(u64 v, float& lo, float& hi) {
    asm("mov.b64 {%0, %1}, %2;" : "=f"(lo), "=f"(hi) : "l"(v));
}

// Warp-wide bitonic sort, ascending, one key per lane.
__device__ __forceinline__ u64 warp_bitonic_sort(u64 key, int lane) {
#pragma unroll
    for (int k = 2; k <= 32; k <<= 1) {
#pragma unroll
        for (int j = k >> 1; j > 0; j >>= 1) {
            u64 other = __shfl_xor_sync(FULLM, key, j);
            bool take_min = (((lane & k) == 0) == ((lane & j) == 0));
            bool lt = key < other;
            key = (take_min == lt) ? key : other;
        }
    }
    return key;
}

// Keep lowest 32 of (top asc-sorted) U (cand asc-sorted), result asc-sorted.
__device__ __forceinline__ u64 warp_merge_topk(u64 top, u64 cand, int lane) {
    u64 crev = __shfl_sync(FULLM, cand, 31 - lane);
    u64 v = (top < crev) ? top : crev;   // bitonic sequence = lowest 32
#pragma unroll
    for (int j = 16; j > 0; j >>= 1) {   // bitonic cleanup
        u64 other = __shfl_xor_sync(FULLM, v, j);
        bool lower = (lane & j) == 0;
        bool lt = v < other;
        v = (lower == lt) ? v : other;
    }
    return v;
}

// Fold full 32-candidate batches from buf into (top, thf).
__device__ __forceinline__ void fold32(u64* buf, int& cnt, u64& top,
                                       float& thf, int lane) {
    while (cnt >= 32) {   // take LAST 32 (order irrelevant: batch gets sorted)
        u64 c = buf[cnt - 32 + lane];
        c   = warp_bitonic_sort(c, lane);
        top = warp_merge_topk(top, c, lane);
        cnt -= 32;
        thf = __uint_as_float((unsigned)(__shfl_sync(FULLM, top, 31) >> 32));
    }
}

// Compact passing lanes of one point-group into buf via ballot.
#define PUSH(buf, cnt, pred, dval, idxval)                                     \
    do {                                                                       \
        unsigned m_ = __ballot_sync(FULLM, pred);                              \
        if (pred) (buf)[(cnt) + __popc(m_ & ltmask)] = pack_key(dval, idxval); \
        (cnt) += __popc(m_);                                                   \
    } while (0)

// ---------------------------------------------------------------------------
// Kernel 1 (fused): blockIdx.x <  KNN_BX -> exact KNN.
//                   blockIdx.x >= KNN_BX -> feature transpose (B,C,N)->(B,N,C).
// The 4096 short transpose blocks backfill the idle tail of the knn wave
// schedule. Slow path is PER-QUERY gated: in the converged phase most entries
// are one-sided, so the other query's 4 ballots+pushes+fold are skipped.
// ---------------------------------------------------------------------------
__global__ __launch_bounds__(WPB * 32)
void knn_tp_kernel(const float* __restrict__ xyz,
                   const float* __restrict__ new_xyz,
                   const float* __restrict__ feat) {
    __shared__ float s_x[TILE], s_y[TILE], s_z[TILE];  // 24 KB (negated)
    __shared__ u64   s_cand[WPB][QPW][CAP];            // 20 KB

    const int b = blockIdx.y;

    if (blockIdx.x >= KNN_BX) {
        // ---- transpose path ----
        float (*t)[33] = (float(*)[33])s_x;   // 32x33 floats, fits in s_x
        const int tb = blockIdx.x - KNN_BX;
        const int n0 = (tb & (NP / 32 - 1)) * 32;
        const int c0 = (tb >> 9) * 32;
        const int tx = threadIdx.x & 31;
        const int ty = threadIdx.x >> 5;      // 0..7
#pragma unroll
        for (int i = 0; i < 4; i++) {
            const int c = c0 + ty + i * 8;
            t[ty + i * 8][tx] = feat[((size_t)b * CF + c) * NP + n0 + tx];
        }
        __syncthreads();
#pragma unroll
        for (int i = 0; i < 4; i++) {
            const int n = n0 + ty + i * 8;
            g_ft[((size_t)b * NP + n) * CF + c0 + tx] = t[tx][ty + i * 8];
        }
        return;
    }

    // ---- knn path ----
    const int warp = threadIdx.x >> 5;
    const int lane = threadIdx.x & 31;
    const int q0   = (blockIdx.x * WPB + warp) * QPW;
    const unsigned ltmask = (1u << lane) - 1u;

    const float* qp = new_xyz + ((size_t)b * NQ + q0) * 3;
    const u64 qxx0 = f2_bcast(qp[0]), qyy0 = f2_bcast(qp[1]), qzz0 = f2_bcast(qp[2]);
    const u64 qxx1 = f2_bcast(qp[3]), qyy1 = f2_bcast(qp[4]), qzz1 = f2_bcast(qp[5]);

    u64 top0 = INFKEY, top1 = INFKEY;
    float thf0 = __int_as_float(0x7f800000);
    float thf1 = __int_as_float(0x7f800000);
    int cnt0 = 0, cnt1 = 0;

    for (int t0 = 0; t0 < NP; t0 += TILE) {
        __syncthreads();
        {
            const float* src = xyz + ((size_t)b * NP + t0) * 3;
#pragma unroll
            for (int k = 0; k < TILE / (WPB * 32); k++) {
                const int pt = threadIdx.x + k * (WPB * 32);
                s_x[pt] = -src[pt * 3];
                s_y[pt] = -src[pt * 3 + 1];
                s_z[pt] = -src[pt * 3 + 2];
            }
        }
        __syncthreads();

#pragma unroll 2
        for (int j = 0; j < TILE; j += 128) {
            const int o = j + 4 * lane;
            const ulonglong2 xs = *(const ulonglong2*)(s_x + o);
            const ulonglong2 ys = *(const ulonglong2*)(s_y + o);
            const ulonglong2 zs = *(const ulonglong2*)(s_z + o);

            // query 0 distances
            u64 a01, a23;
            {
                const u64 dx01 = f2_add(qxx0, xs.x), dx23 = f2_add(qxx0, xs.y);
                const u64 dy01 = f2_add(qyy0, ys.x), dy23 = f2_add(qyy0, ys.y);
                const u64 dz01 = f2_add(qzz0, zs.x), dz23 = f2_add(qzz0, zs.y);
                a01 = f2_mul(dz01, dz01);
                a23 = f2_mul(dz23, dz23);
                a01 = f2_fma(dy01, dy01, a01);
                a23 = f2_fma(dy23, dy23, a23);
                a01 = f2_fma(dx01, dx01, a01);
                a23 = f2_fma(dx23, dx23, a23);
            }
            // query 1 distances
            u64 b01, b23;
            {
                const u64 dx01 = f2_add(qxx1, xs.x), dx23 = f2_add(qxx1, xs.y);
                const u64 dy01 = f2_add(qyy1, ys.x), dy23 = f2_add(qyy1, ys.y);
                const u64 dz01 = f2_add(qzz1, zs.x), dz23 = f2_add(qzz1, zs.y);
                b01 = f2_mul(dz01, dz01);
                b23 = f2_mul(dz23, dz23);
                b01 = f2_fma(dy01, dy01, b01);
                b23 = f2_fma(dy23, dy23, b23);
                b01 = f2_fma(dx01, dx01, b01);
                b23 = f2_fma(dx23, dx23, b23);
            }

            float d0, d1, d2, d3, e0, e1, e2, e3;
            f2_unpack(a01, d0, d1);  f2_unpack(a23, d2, d3);
            f2_unpack(b01, e0, e1);  f2_unpack(b23, e2, e3);

            const bool hit0 = fminf(fminf(d0, d1), fminf(d2, d3)) < thf0;
            const bool hit1 = fminf(fminf(e0, e1), fminf(e2, e3)) < thf1;
            if (__any_sync(FULLM, hit0 | hit1)) {
                const int gi = t0 + o;
                // per-query gates: skip the whole block when one-sided
                if (__ballot_sync(FULLM, hit0)) {
                    PUSH(s_cand[warp][0], cnt0, d0 < thf0, d0, gi);
                    PUSH(s_cand[warp][0], cnt0, d1 < thf0, d1, gi + 1);
                    PUSH(s_cand[warp][0], cnt0, d2 < thf0, d2, gi + 2);
                    PUSH(s_cand[warp][0], cnt0, d3 < thf0, d3, gi + 3);
                    __syncwarp(FULLM);
                    fold32(s_cand[warp][0], cnt0, top0, thf0, lane);
                }
                if (__ballot_sync(FULLM, hit1)) {
                    PUSH(s_cand[warp][1], cnt1, e0 < thf1, e0, gi);
                    PUSH(s_cand[warp][1], cnt1, e1 < thf1, e1, gi + 1);
                    PUSH(s_cand[warp][1], cnt1, e2 < thf1, e2, gi + 2);
                    PUSH(s_cand[warp][1], cnt1, e3 < thf1, e3, gi + 3);
                    __syncwarp(FULLM);
                    fold32(s_cand[warp][1], cnt1, top1, thf1, lane);
                }
            }
        }
    }
    __syncwarp(FULLM);
    if (cnt0 > 0) {
        u64 c = (lane < cnt0) ? s_cand[warp][0][lane] : INFKEY;
        c = warp_bitonic_sort(c, lane);
        top0 = warp_merge_topk(top0, c, lane);
    }
    if (cnt1 > 0) {
        u64 c = (lane < cnt1) ? s_cand[warp][1][lane] : INFKEY;
        c = warp_bitonic_sort(c, lane);
        top1 = warp_merge_topk(top1, c, lane);
    }

    // tops are ascending by (dist, idx) -> slot order matches top_k output.
    g_idx[((size_t)b * NQ + q0) * KS + lane]     = (int)(top0 & 0xffffffffu);
    g_idx[((size_t)b * NQ + q0 + 1) * KS + lane] = (int)(top1 & 0xffffffffu);
}

// ---------------------------------------------------------------------------
// Kernel 2: gather / center / transpose / concat. TWO adjacent queries per
// 256-thread block. Staging: coalesced 256B feature-row reads -> smem.
// Output: for a fixed channel c the rows of p0 and p1 are CONTIGUOUS (256B),
// so one warp writes both queries' channel row with a single STG.64 per lane
// (lane<16 -> p0, lane>=16 -> p1). 8 warps stride over the 67 channels.
// ---------------------------------------------------------------------------
__global__ __launch_bounds__(256)
void group_kernel(const float* __restrict__ xyz,
                  const float* __restrict__ new_xyz,
                  float* __restrict__ out) {
    const int b    = blockIdx.y;
    const int p0   = blockIdx.x * 2;
    const int tid  = threadIdx.x;
    const int half = tid >> 7;               // 0 or 1 (staging query)
    const int t    = tid & 127;
    const int w    = t >> 5;
    const int lane = t & 31;

    __shared__ int   sidx[2][KS];
    __shared__ float sfeat[2][KS][65];

    if (t < KS) sidx[half][t] = g_idx[((size_t)b * NQ + p0 + half) * KS + t];
    __syncthreads();

    // Stage neighbor feature rows: warp w loads rows w, w+4, ... (256B each).
    for (int s = w; s < KS; s += 4) {
        const float2* row =
            (const float2*)(g_ft + ((size_t)b * NP + sidx[half][s]) * CF);
        const float2 v = row[lane];
        sfeat[half][s][lane * 2]     = v.x;
        sfeat[half][s][lane * 2 + 1] = v.y;
    }
    __syncthreads();

    // Output: warp ww owns channels ww, ww+8, ... Each lane supplies the
    // float2 (s0, s0+1) of query h; lane*8B spans p0's then p1's 128B row.
    const int ww = tid >> 5;                 // 0..7
    const int l  = tid & 31;
    const int h  = l >> 4;                   // query half for this lane
    const int s0 = (l & 15) * 2;
    const int i0 = sidx[h][s0];
    const int i1 = sidx[h][s0 + 1];

    for (int c = ww; c < OUTC; c += 8) {
        float v0, v1;
        if (c < 3) {
            const float q = new_xyz[((size_t)b * NQ + p0 + h) * 3 + c];
            v0 = xyz[((size_t)b * NP + i0) * 3 + c] - q;
            v1 = xyz[((size_t)b * NP + i1) * 3 + c] - q;
        } else {
            v0 = sfeat[h][s0][c - 3];
            v1 = sfeat[h][s0 + 1][c - 3];
        }
        float2* dst =
            (float2*)(out + (((size_t)b * OUTC + c) * NQ + p0) * KS);
        dst[l] = make_float2(v0, v1);
    }
}

extern "C" void kernel_launch(void* const* d_in, const int* in_sizes, int n_in,
                              void* d_out, int out_size) {
    const float* xyz     = (const float*)d_in[0];  // (B, N, 3)
    const float* new_xyz = (const float*)d_in[1];  // (B, NPOINT, 3)
    const float* feat    = (const float*)d_in[2];  // (B, C, N)
    float* out = (float*)d_out;                    // (B, 67, NPOINT, 32)

    // Fused knn + transpose: knn blocks first (long), transpose blocks
    // backfill the wave tail.
    dim3 g1(KNN_BX + TP_BX, BQ);
    knn_tp_kernel<<<g1, WPB * 32>>>(xyz, new_xyz, feat);

    dim3 g2(NQ / 2, BQ);
    group_kernel<<<g2, 256>>>(xyz, new_xyz, out);
}